// round 1
// baseline (speedup 1.0000x reference)
#include <cuda_runtime.h>

// Problem constants
#define BB   32
#define TT   256
#define FF   224
#define EE   32
#define NHH  4
#define DHH  64
#define DD   256   // F + E
#define HH   256   // NH * DH
#define ROWS (BB*TT)   // 8192

// ---------------- scratch (static device globals; no allocation) ------------
__device__ float g_x [ROWS*DD];   // residual stream
__device__ float g_xn[ROWS*DD];   // layernorm output
__device__ float g_g0[ROWS*HH];   // q / z
__device__ float g_g1[ROWS*HH];   // k / i
__device__ float g_g2[ROWS*HH];   // v / f
__device__ float g_g3[ROWS*HH];   // o / o
__device__ float g_h [ROWS*HH];   // scan output
__device__ float g_ip[ROWS*NHH];
__device__ float g_fp[ROWS*NHH];

__device__ __forceinline__ float* bufsel(int s) {
    switch (s) {
        case 0: return g_x;
        case 1: return g_xn;
        case 2: return g_g0;
        case 3: return g_g1;
        case 4: return g_g2;
        case 5: return g_g3;
        default: return g_h;
    }
}

#define SEL_X  0
#define SEL_XN 1
#define SEL_G0 2
#define SEL_G1 3
#define SEL_G2 4
#define SEL_G3 5
#define SEL_H  6

// ---------------- input assembly: concat(X, embed[dyad]) --------------------
__global__ void build_x(const float* __restrict__ X,
                        const int*   __restrict__ dyad,
                        const float* __restrict__ embed) {
    int row = blockIdx.x;       // b*T + t
    int f   = threadIdx.x;      // 0..255
    int b   = row / TT;
    float v;
    if (f < FF) v = X[row*FF + f];
    else        v = embed[dyad[b]*EE + (f - FF)];
    g_x[row*DD + f] = v;
}

// ---------------- LayerNorm over last dim (256) ------------------------------
__global__ void ln_kernel(const float* __restrict__ gam,
                          const float* __restrict__ bet) {
    int row = blockIdx.x, t = threadIdx.x;
    float x  = g_x[row*DD + t];
    float s  = x, s2 = x*x;
    #pragma unroll
    for (int off = 16; off; off >>= 1) {
        s  += __shfl_xor_sync(0xffffffffu, s,  off);
        s2 += __shfl_xor_sync(0xffffffffu, s2, off);
    }
    __shared__ float a1[8], a2[8];
    __shared__ float smu, srs;
    if ((t & 31) == 0) { a1[t >> 5] = s; a2[t >> 5] = s2; }
    __syncthreads();
    if (t == 0) {
        float u = 0.f, u2 = 0.f;
        #pragma unroll
        for (int i = 0; i < 8; i++) { u += a1[i]; u2 += a2[i]; }
        float mu  = u  * (1.0f/DD);
        float var = u2 * (1.0f/DD) - mu*mu;
        smu = mu;
        srs = rsqrtf(var + 1e-5f);
    }
    __syncthreads();
    g_xn[row*DD + t] = (x - smu) * srs * gam[t] + bet[t];
}

// ---------------- SGEMM: C[8192,256] (+)= A[8192,256] @ B[256,256] ----------
#define BM 128
#define BN 128
#define BKK 8

__global__ void __launch_bounds__(256)
sgemm_k(int aSel, const float* __restrict__ Bw, int cSel, int useRes) {
    const float* A = bufsel(aSel);
    float*       C = bufsel(cSel);
    const int K = DD, N = HH;

    __shared__ __align__(16) float As[BKK][BM];
    __shared__ __align__(16) float Bs[BKK][BN];

    int tid = threadIdx.x;
    int rowBase = blockIdx.y * BM, colBase = blockIdx.x * BN;

    int aRow = tid >> 1,  aCol = (tid & 1) * 4;   // A tile: 128x8, 1 float4/thr
    int bRow = tid >> 5,  bCol = (tid & 31) * 4;  // B tile: 8x128, 1 float4/thr
    int tx = (tid & 15) * 8, ty = (tid >> 4) * 8; // 16x16 thread grid, 8x8 each

    float acc[8][8];
    #pragma unroll
    for (int i = 0; i < 8; i++)
        #pragma unroll
        for (int j = 0; j < 8; j++) acc[i][j] = 0.f;

    const float* Aptr = A  + (size_t)(rowBase + aRow) * K + aCol;
    const float* Bptr = Bw + (size_t)bRow * N + colBase + bCol;

    float4 av = *(const float4*)Aptr;
    float4 bv = *(const float4*)Bptr;

    for (int k0 = 0; k0 < K; k0 += BKK) {
        As[aCol+0][aRow] = av.x; As[aCol+1][aRow] = av.y;
        As[aCol+2][aRow] = av.z; As[aCol+3][aRow] = av.w;
        *(float4*)&Bs[bRow][bCol] = bv;
        __syncthreads();

        if (k0 + BKK < K) {
            av = *(const float4*)(Aptr + k0 + BKK);
            bv = *(const float4*)(Bptr + (size_t)(k0 + BKK) * N);
        }

        #pragma unroll
        for (int k = 0; k < BKK; k++) {
            float4 a0 = *(const float4*)&As[k][ty];
            float4 a1 = *(const float4*)&As[k][ty+4];
            float4 b0 = *(const float4*)&Bs[k][tx];
            float4 b1 = *(const float4*)&Bs[k][tx+4];
            float ar[8] = {a0.x,a0.y,a0.z,a0.w,a1.x,a1.y,a1.z,a1.w};
            float br[8] = {b0.x,b0.y,b0.z,b0.w,b1.x,b1.y,b1.z,b1.w};
            #pragma unroll
            for (int i = 0; i < 8; i++)
                #pragma unroll
                for (int j = 0; j < 8; j++)
                    acc[i][j] = fmaf(ar[i], br[j], acc[i][j]);
        }
        __syncthreads();
    }

    #pragma unroll
    for (int i = 0; i < 8; i++) {
        int row = rowBase + ty + i;
        float* Cp = C + (size_t)row * N + colBase + tx;
        if (useRes) {   // residual accumulate in place (C holds residual stream)
            #pragma unroll
            for (int j = 0; j < 8; j++) Cp[j] += acc[i][j];
        } else {
            *(float4*)(Cp)   = make_float4(acc[i][0], acc[i][1], acc[i][2], acc[i][3]);
            *(float4*)(Cp+4) = make_float4(acc[i][4], acc[i][5], acc[i][6], acc[i][7]);
        }
    }
}

// ---------------- mLSTM scalar gate preactivations (ip, fp) -----------------
__global__ void ipfp_kernel(const float* __restrict__ Wi,
                            const float* __restrict__ Wf,
                            const float* __restrict__ bi,
                            const float* __restrict__ bf) {
    int gi   = blockIdx.x * blockDim.x + threadIdx.x;  // < 65536
    int row  = gi >> 3;
    int r    = gi & 7;
    int gate = r >> 2;     // 0=i, 1=f
    int nh   = r & 3;
    const float* W = gate ? Wf : Wi;
    float acc = gate ? bf[nh] : bi[nh];
    const float* xr = g_xn + (size_t)row * DD;
    #pragma unroll 8
    for (int k = 0; k < DD; k++) acc = fmaf(xr[k], W[k*NHH + nh], acc);
    if (gate) g_fp[row*NHH + nh] = acc;
    else      g_ip[row*NHH + nh] = acc;
}

// ---------------- mLSTM recurrent scan (one block per (b,head)) -------------
__global__ void __launch_bounds__(256) mlstm_scan() {
    int b  = blockIdx.x >> 2;
    int nh = blockIdx.x & 3;
    int t  = threadIdx.x;
    int d  = t >> 2;            // 0..63
    int es = t & 3;             // e-subrange
    int e0 = es * 16;

    float Creg[16];
    #pragma unroll
    for (int i = 0; i < 16; i++) Creg[i] = 0.f;
    float n_d = 0.f, m = 0.f;

    __shared__ __align__(16) float sq[64], sk[64], sv[64], so[64];
    __shared__ float red[64];
    __shared__ float s_den;

    for (int tt = 0; tt < TT; tt++) {
        int row = b*TT + tt;
        {   // load q,k,v,o for this step: 256 threads cover 4 gates x 64
            int g = t >> 6, idx = t & 63;
            const float* src = (g==0) ? g_g0 : (g==1) ? g_g1 : (g==2) ? g_g2 : g_g3;
            float val = src[(size_t)row*HH + nh*DHH + idx];
            if (g == 1) val *= 0.125f;                       // k * DH^-0.5
            if (g == 3) val = 1.f / (1.f + expf(-val));      // sigmoid(o)
            float* dst = (g==0) ? sq : (g==1) ? sk : (g==2) ? sv : so;
            dst[idx] = val;
        }
        float ip = g_ip[row*NHH + nh];
        float fp = g_fp[row*NHH + nh];
        float mn  = fmaxf(fp + m, ip);
        float i_s = expf(ip - mn);
        float f_s = expf(fp + m - mn);
        m = mn;
        __syncthreads();                        // gates visible

        float vd = sv[d];
        float qp = 0.f;
        #pragma unroll
        for (int i4 = 0; i4 < 4; i4++) {
            float4 k4 = *(const float4*)&sk[e0 + i4*4];
            float4 q4 = *(const float4*)&sq[e0 + i4*4];
            float* c = &Creg[i4*4];
            c[0] = fmaf(f_s, c[0], i_s*vd*k4.x); qp = fmaf(c[0], q4.x, qp);
            c[1] = fmaf(f_s, c[1], i_s*vd*k4.y); qp = fmaf(c[1], q4.y, qp);
            c[2] = fmaf(f_s, c[2], i_s*vd*k4.z); qp = fmaf(c[2], q4.z, qp);
            c[3] = fmaf(f_s, c[3], i_s*vd*k4.w); qp = fmaf(c[3], q4.w, qp);
        }
        qp += __shfl_xor_sync(0xffffffffu, qp, 1);
        qp += __shfl_xor_sync(0xffffffffu, qp, 2);

        n_d = fmaf(f_s, n_d, i_s * sk[d]);
        float ovald = so[d];                    // read before sync2
        if (es == 0) red[d] = n_d * sq[d];
        __syncthreads();                        // red ready

        if (t < 32) {
            float s = red[t] + red[t + 32];
            #pragma unroll
            for (int off = 16; off; off >>= 1)
                s += __shfl_xor_sync(0xffffffffu, s, off);
            if (t == 0) s_den = fmaxf(fabsf(s), 1.0f);
        }
        __syncthreads();                        // s_den ready

        if (es == 0)
            g_h[(size_t)row*HH + nh*DHH + d] = ovald * qp / s_den;
    }
}

// ---------------- sLSTM recurrent scan (one block per (b,head)) -------------
__global__ void __launch_bounds__(256) slstm_scan(const float* __restrict__ Rz,
                                                  const float* __restrict__ Ri,
                                                  const float* __restrict__ Rf,
                                                  const float* __restrict__ Ro) {
    int b  = blockIdx.x >> 2;
    int nh = blockIdx.x & 3;
    int t  = threadIdx.x;
    int g  = t >> 6;       // gate: 0=z 1=i 2=f 3=o
    int e  = t & 63;

    const float* Rg = ((g==0) ? Rz : (g==1) ? Ri : (g==2) ? Rf : Ro) + nh*DHH*DHH;
    float Rcol[64];
    #pragma unroll
    for (int d = 0; d < 64; d++) Rcol[d] = Rg[d*64 + e];   // coalesced per d

    const float* gb = (g==0) ? g_g0 : (g==1) ? g_g1 : (g==2) ? g_g2 : g_g3;

    __shared__ __align__(16) float sh[64];
    __shared__ float spre[4][64];
    if (t < 64) sh[t] = 0.f;
    float c = 0.f, n = 0.f, m = 0.f;
    __syncthreads();

    for (int tt = 0; tt < TT; tt++) {
        int row = b*TT + tt;
        float pre = gb[(size_t)row*HH + nh*DHH + e];
        float r = 0.f;
        #pragma unroll
        for (int d4 = 0; d4 < 16; d4++) {
            float4 h4 = *(const float4*)&sh[d4*4];
            r = fmaf(h4.x, Rcol[d4*4+0], r);
            r = fmaf(h4.y, Rcol[d4*4+1], r);
            r = fmaf(h4.z, Rcol[d4*4+2], r);
            r = fmaf(h4.w, Rcol[d4*4+3], r);
        }
        spre[g][e] = pre + r;
        __syncthreads();                        // A: spre ready

        if (t < 64) {
            float z   = tanhf(spre[0][e]);
            float ipp = spre[1][e];
            float fpp = spre[2][e];
            float o   = 1.f / (1.f + expf(-spre[3][e]));
            float mn  = fmaxf(fpp + m, ipp);
            float i_s = expf(ipp - mn);
            float f_s = expf(fpp + m - mn);
            m = mn;
            c = fmaf(f_s, c, i_s * z);
            n = fmaf(f_s, n, i_s);
            float h = o * c / n;
            sh[e] = h;
            g_h[(size_t)row*HH + nh*DHH + e] = h;
        }
        __syncthreads();                        // B: sh ready for next step
    }
}

// ---------------- head: out[b] = x[b,T-1,:] . fc_W + fc_b -------------------
__global__ void final_kernel(const float* __restrict__ fcW,
                             const float* __restrict__ fcb,
                             float* __restrict__ out) {
    int bI = blockIdx.x, t = threadIdx.x;
    float v = g_x[(size_t)(bI*TT + TT-1)*DD + t] * fcW[t];
    #pragma unroll
    for (int off = 16; off; off >>= 1)
        v += __shfl_xor_sync(0xffffffffu, v, off);
    __shared__ float a[8];
    if ((t & 31) == 0) a[t >> 5] = v;
    __syncthreads();
    if (t == 0) {
        float s = 0.f;
        #pragma unroll
        for (int i = 0; i < 8; i++) s += a[i];
        out[bI] = s + fcb[0];
    }
}

// ---------------- launch sequence -------------------------------------------
extern "C" void kernel_launch(void* const* d_in, const int* in_sizes, int n_in,
                              void* d_out, int out_size) {
    const float* X      = (const float*)d_in[0];
    const int*   dyad   = (const int*)  d_in[1];
    const float* embed  = (const float*)d_in[2];
    const float* m_ln_g = (const float*)d_in[3];
    const float* m_ln_b = (const float*)d_in[4];
    const float* m_Wq   = (const float*)d_in[5];
    const float* m_Wk   = (const float*)d_in[6];
    const float* m_Wv   = (const float*)d_in[7];
    const float* m_Wi   = (const float*)d_in[8];
    const float* m_Wf   = (const float*)d_in[9];
    const float* m_bi   = (const float*)d_in[10];
    const float* m_bf   = (const float*)d_in[11];
    const float* m_Wo   = (const float*)d_in[12];
    const float* m_Wp   = (const float*)d_in[13];
    const float* s_ln_g = (const float*)d_in[14];
    const float* s_ln_b = (const float*)d_in[15];
    const float* s_Wz   = (const float*)d_in[16];
    const float* s_Wi   = (const float*)d_in[17];
    const float* s_Wf   = (const float*)d_in[18];
    const float* s_Wo   = (const float*)d_in[19];
    const float* s_Rz   = (const float*)d_in[20];
    const float* s_Ri   = (const float*)d_in[21];
    const float* s_Rf   = (const float*)d_in[22];
    const float* s_Ro   = (const float*)d_in[23];
    const float* s_Wp   = (const float*)d_in[24];
    const float* fc_W   = (const float*)d_in[25];
    const float* fc_b   = (const float*)d_in[26];
    float* out = (float*)d_out;

    dim3 gg(HH/BN, ROWS/BM);   // (2, 64)

    build_x<<<ROWS, 256>>>(X, dyad, embed);

    // ---- mLSTM layer 0 ----
    ln_kernel<<<ROWS, 256>>>(m_ln_g, m_ln_b);
    sgemm_k<<<gg, 256>>>(SEL_XN, m_Wq, SEL_G0, 0);
    sgemm_k<<<gg, 256>>>(SEL_XN, m_Wk, SEL_G1, 0);
    sgemm_k<<<gg, 256>>>(SEL_XN, m_Wv, SEL_G2, 0);
    sgemm_k<<<gg, 256>>>(SEL_XN, m_Wo, SEL_G3, 0);
    ipfp_kernel<<<(ROWS*NHH*2)/256, 256>>>(m_Wi, m_Wf, m_bi, m_bf);
    mlstm_scan<<<BB*NHH, 256>>>();
    sgemm_k<<<gg, 256>>>(SEL_H, m_Wp, SEL_X, 1);

    // ---- sLSTM layer ----
    ln_kernel<<<ROWS, 256>>>(s_ln_g, s_ln_b);
    sgemm_k<<<gg, 256>>>(SEL_XN, s_Wz, SEL_G0, 0);
    sgemm_k<<<gg, 256>>>(SEL_XN, s_Wi, SEL_G1, 0);
    sgemm_k<<<gg, 256>>>(SEL_XN, s_Wf, SEL_G2, 0);
    sgemm_k<<<gg, 256>>>(SEL_XN, s_Wo, SEL_G3, 0);
    slstm_scan<<<BB*NHH, 256>>>(s_Rz, s_Ri, s_Rf, s_Ro);
    sgemm_k<<<gg, 256>>>(SEL_H, s_Wp, SEL_X, 1);

    // ---- mLSTM layer 1 ----
    ln_kernel<<<ROWS, 256>>>(m_ln_g + DD, m_ln_b + DD);
    sgemm_k<<<gg, 256>>>(SEL_XN, m_Wq + DD*HH, SEL_G0, 0);
    sgemm_k<<<gg, 256>>>(SEL_XN, m_Wk + DD*HH, SEL_G1, 0);
    sgemm_k<<<gg, 256>>>(SEL_XN, m_Wv + DD*HH, SEL_G2, 0);
    sgemm_k<<<gg, 256>>>(SEL_XN, m_Wo + DD*HH, SEL_G3, 0);
    ipfp_kernel<<<(ROWS*NHH*2)/256, 256>>>(m_Wi + DD*NHH, m_Wf + DD*NHH,
                                           m_bi + NHH, m_bf + NHH);
    mlstm_scan<<<BB*NHH, 256>>>();
    sgemm_k<<<gg, 256>>>(SEL_H, m_Wp + HH*DD, SEL_X, 1);

    final_kernel<<<BB, 256>>>(fc_W, fc_b, out);
    (void)in_sizes; (void)n_in; (void)out_size;
}

// round 2
// speedup vs baseline: 1.4578x; 1.4578x over previous
#include <cuda_runtime.h>

// Problem constants
#define BB   32
#define TT   256
#define FF   224
#define EE   32
#define NHH  4
#define DHH  64
#define DD   256   // F + E
#define HH   256   // NH * DH
#define ROWS (BB*TT)   // 8192

// ---------------- scratch (static device globals; no allocation) ------------
__device__ float g_x [ROWS*DD];   // residual stream
__device__ float g_xn[ROWS*DD];   // layernorm output
__device__ float g_g0[ROWS*HH];   // q / z
__device__ float g_g1[ROWS*HH];   // k / i
__device__ float g_g2[ROWS*HH];   // v / f
__device__ float g_g3[ROWS*HH];   // o / o
__device__ float g_h [ROWS*HH];   // scan output
__device__ float g_ip[ROWS*NHH];
__device__ float g_fp[ROWS*NHH];

__device__ __forceinline__ float* bufsel(int s) {
    switch (s) {
        case 0: return g_x;
        case 1: return g_xn;
        default: return g_h;
    }
}
#define SEL_X  0
#define SEL_XN 1
#define SEL_H  2

// ---------------- input assembly: concat(X, embed[dyad]) --------------------
__global__ void build_x(const float* __restrict__ X,
                        const int*   __restrict__ dyad,
                        const float* __restrict__ embed) {
    int row = blockIdx.x;
    int f   = threadIdx.x;
    int b   = row / TT;
    float v;
    if (f < FF) v = X[row*FF + f];
    else        v = embed[dyad[b]*EE + (f - FF)];
    g_x[row*DD + f] = v;
}

// ---------------- LayerNorm over last dim (256) ------------------------------
__global__ void ln_kernel(const float* __restrict__ gam,
                          const float* __restrict__ bet) {
    int row = blockIdx.x, t = threadIdx.x;
    float x  = g_x[row*DD + t];
    float s  = x, s2 = x*x;
    #pragma unroll
    for (int off = 16; off; off >>= 1) {
        s  += __shfl_xor_sync(0xffffffffu, s,  off);
        s2 += __shfl_xor_sync(0xffffffffu, s2, off);
    }
    __shared__ float a1[8], a2[8];
    __shared__ float smu, srs;
    if ((t & 31) == 0) { a1[t >> 5] = s; a2[t >> 5] = s2; }
    __syncthreads();
    if (t == 0) {
        float u = 0.f, u2 = 0.f;
        #pragma unroll
        for (int i = 0; i < 8; i++) { u += a1[i]; u2 += a2[i]; }
        float mu  = u  * (1.0f/DD);
        float var = u2 * (1.0f/DD) - mu*mu;
        smu = mu;
        srs = rsqrtf(var + 1e-5f);
    }
    __syncthreads();
    g_xn[row*DD + t] = (x - smu) * srs * gam[t] + bet[t];
}

// ---------------- shared 128x64 fp32 GEMM tile -------------------------------
#define GBM 128
#define GBN 64
#define GBK 8

__device__ __forceinline__ void gemm_tile128x64(const float* __restrict__ A,
                                                const float* __restrict__ Bw,
                                                int rowBase, int colBase,
                                                float (&acc)[8][4]) {
    const int K = DD, N = HH;
    __shared__ __align__(16) float As[GBK][GBM];
    __shared__ __align__(16) float Bs[GBK][GBN];
    int tid  = threadIdx.x;
    int aRow = tid >> 1,  aCol = (tid & 1) * 4;    // 128x8, float4/thr
    int bRow = tid >> 5,  bCol = (tid & 31) * 2;   // 8x64,  float2/thr
    int tx = (tid & 15) * 4, ty = (tid >> 4) * 8;

    #pragma unroll
    for (int i = 0; i < 8; i++)
        #pragma unroll
        for (int j = 0; j < 4; j++) acc[i][j] = 0.f;

    const float* Aptr = A  + (size_t)(rowBase + aRow) * K + aCol;
    const float* Bptr = Bw + (size_t)bRow * N + colBase + bCol;

    float4 av = *(const float4*)Aptr;
    float2 bv = *(const float2*)Bptr;

    for (int k0 = 0; k0 < K; k0 += GBK) {
        As[aCol+0][aRow] = av.x; As[aCol+1][aRow] = av.y;
        As[aCol+2][aRow] = av.z; As[aCol+3][aRow] = av.w;
        *(float2*)&Bs[bRow][bCol] = bv;
        __syncthreads();

        if (k0 + GBK < K) {
            av = *(const float4*)(Aptr + k0 + GBK);
            bv = *(const float2*)(Bptr + (size_t)(k0 + GBK) * N);
        }

        #pragma unroll
        for (int k = 0; k < GBK; k++) {
            float4 a0 = *(const float4*)&As[k][ty];
            float4 a1 = *(const float4*)&As[k][ty+4];
            float4 b0 = *(const float4*)&Bs[k][tx];
            float ar[8] = {a0.x,a0.y,a0.z,a0.w,a1.x,a1.y,a1.z,a1.w};
            float br[4] = {b0.x,b0.y,b0.z,b0.w};
            #pragma unroll
            for (int i = 0; i < 8; i++)
                #pragma unroll
                for (int j = 0; j < 4; j++)
                    acc[i][j] = fmaf(ar[i], br[j], acc[i][j]);
        }
        __syncthreads();
    }
}

// ---------------- fused 4-gate GEMM (one launch per layer) -------------------
// grid: (16, 64).  blockIdx.x: w = x>>2 selects weight/output, x&3 col tile.
// mTrans: mLSTM transforms (w==1 -> *DH^-0.5 ; w==3 -> sigmoid)
__global__ void __launch_bounds__(256) gemm_gates(
    int aSel,
    const float* __restrict__ W0, const float* __restrict__ W1,
    const float* __restrict__ W2, const float* __restrict__ W3,
    int mTrans)
{
    int w       = blockIdx.x >> 2;
    int colBase = (blockIdx.x & 3) * GBN;
    int rowBase = blockIdx.y * GBM;
    const float* Bw = (w==0) ? W0 : (w==1) ? W1 : (w==2) ? W2 : W3;
    float*       C  = (w==0) ? g_g0 : (w==1) ? g_g1 : (w==2) ? g_g2 : g_g3;
    const float* A  = bufsel(aSel);

    float acc[8][4];
    gemm_tile128x64(A, Bw, rowBase, colBase, acc);

    int tx = (threadIdx.x & 15) * 4, ty = (threadIdx.x >> 4) * 8;
    #pragma unroll
    for (int i = 0; i < 8; i++) {
        float4 v = make_float4(acc[i][0], acc[i][1], acc[i][2], acc[i][3]);
        if (mTrans) {
            if (w == 1) { v.x *= 0.125f; v.y *= 0.125f; v.z *= 0.125f; v.w *= 0.125f; }
            else if (w == 3) {
                v.x = 1.f/(1.f+expf(-v.x)); v.y = 1.f/(1.f+expf(-v.y));
                v.z = 1.f/(1.f+expf(-v.z)); v.w = 1.f/(1.f+expf(-v.w));
            }
        }
        *(float4*)(C + (size_t)(rowBase + ty + i) * HH + colBase + tx) = v;
    }
}

// ---------------- single GEMM with residual accumulate (Wp) ------------------
// grid: (4, 64)
__global__ void __launch_bounds__(256) gemm_res(
    int aSel, const float* __restrict__ Bw, int cSel)
{
    int colBase = blockIdx.x * GBN;
    int rowBase = blockIdx.y * GBM;
    const float* A = bufsel(aSel);
    float*       C = bufsel(cSel);

    float acc[8][4];
    gemm_tile128x64(A, Bw, rowBase, colBase, acc);

    int tx = (threadIdx.x & 15) * 4, ty = (threadIdx.x >> 4) * 8;
    #pragma unroll
    for (int i = 0; i < 8; i++) {
        float* Cp = C + (size_t)(rowBase + ty + i) * HH + colBase + tx;
        float4 c = *(const float4*)Cp;
        c.x += acc[i][0]; c.y += acc[i][1]; c.z += acc[i][2]; c.w += acc[i][3];
        *(float4*)Cp = c;
    }
}

// ---------------- mLSTM scalar gate preactivations (ip, fp) -----------------
__global__ void ipfp_kernel(const float* __restrict__ Wi,
                            const float* __restrict__ Wf,
                            const float* __restrict__ bi,
                            const float* __restrict__ bf) {
    int gi   = blockIdx.x * blockDim.x + threadIdx.x;
    int row  = gi >> 3;
    int r    = gi & 7;
    int gate = r >> 2;
    int nh   = r & 3;
    const float* W = gate ? Wf : Wi;
    float acc = gate ? bf[nh] : bi[nh];
    const float* xr = g_xn + (size_t)row * DD;
    #pragma unroll 8
    for (int k = 0; k < DD; k++) acc = fmaf(xr[k], W[k*NHH + nh], acc);
    if (gate) g_fp[row*NHH + nh] = acc;
    else      g_ip[row*NHH + nh] = acc;
}

// ---------------- mLSTM recurrent scan (one block per (b,head)) -------------
// gates are pre-transformed by GEMM epilogue (k scaled, o sigmoided).
__global__ void __launch_bounds__(256) mlstm_scan() {
    int b  = blockIdx.x >> 2;
    int nh = blockIdx.x & 3;
    int t  = threadIdx.x;
    int d  = t >> 2;            // 0..63
    int es = t & 3;
    int e0 = es * 16;
    int g   = t >> 6, idx = t & 63;

    const float* src = (g==0) ? g_g0 : (g==1) ? g_g1 : (g==2) ? g_g2 : g_g3;
    const float* gp  = src + (size_t)(b*TT)*HH + nh*DHH + idx;
    const float* ipp = g_ip + (size_t)(b*TT)*NHH + nh;
    const float* fpp = g_fp + (size_t)(b*TT)*NHH + nh;

    float Creg[16];
    #pragma unroll
    for (int i = 0; i < 16; i++) Creg[i] = 0.f;
    float n_d = 0.f, m = 0.f;

    __shared__ __align__(16) float sq[64], sk[64], sv[64], so[64];
    __shared__ float red[64];
    __shared__ float s_den;
    float* dst = (g==0) ? sq : (g==1) ? sk : (g==2) ? sv : so;

    // prefetch step 0
    float val = gp[0];
    float ipc = ipp[0];
    float fpc = fpp[0];

    for (int tt = 0; tt < TT; tt++) {
        dst[idx] = val;
        float mn  = fmaxf(fpc + m, ipc);
        float i_s = expf(ipc - mn);
        float f_s = expf(fpc + m - mn);
        m = mn;
        __syncthreads();                        // gates visible

        // prefetch next step (hidden behind compute + 2 barriers)
        if (tt + 1 < TT) {
            val = gp[(size_t)(tt+1) * HH];
            ipc = ipp[(tt+1) * NHH];
            fpc = fpp[(tt+1) * NHH];
        }

        float vd = sv[d];
        float qp = 0.f;
        #pragma unroll
        for (int i4 = 0; i4 < 4; i4++) {
            float4 k4 = *(const float4*)&sk[e0 + i4*4];
            float4 q4 = *(const float4*)&sq[e0 + i4*4];
            float* c = &Creg[i4*4];
            c[0] = fmaf(f_s, c[0], i_s*vd*k4.x); qp = fmaf(c[0], q4.x, qp);
            c[1] = fmaf(f_s, c[1], i_s*vd*k4.y); qp = fmaf(c[1], q4.y, qp);
            c[2] = fmaf(f_s, c[2], i_s*vd*k4.z); qp = fmaf(c[2], q4.z, qp);
            c[3] = fmaf(f_s, c[3], i_s*vd*k4.w); qp = fmaf(c[3], q4.w, qp);
        }
        qp += __shfl_xor_sync(0xffffffffu, qp, 1);
        qp += __shfl_xor_sync(0xffffffffu, qp, 2);

        n_d = fmaf(f_s, n_d, i_s * sk[d]);
        float ovald = so[d];
        if (es == 0) red[d] = n_d * sq[d];
        __syncthreads();                        // red ready

        if (t < 32) {
            float s = red[t] + red[t + 32];
            #pragma unroll
            for (int off = 16; off; off >>= 1)
                s += __shfl_xor_sync(0xffffffffu, s, off);
            if (t == 0) s_den = fmaxf(fabsf(s), 1.0f);
        }
        __syncthreads();                        // s_den ready

        if (es == 0)
            g_h[(size_t)(b*TT + tt)*HH + nh*DHH + d] = ovald * qp / s_den;
    }
}

// ---------------- sLSTM recurrent scan (one block per (b,head)) -------------
__global__ void __launch_bounds__(256) slstm_scan(const float* __restrict__ Rz,
                                                  const float* __restrict__ Ri,
                                                  const float* __restrict__ Rf,
                                                  const float* __restrict__ Ro) {
    int b  = blockIdx.x >> 2;
    int nh = blockIdx.x & 3;
    int t  = threadIdx.x;
    int g  = t >> 6;
    int e  = t & 63;

    const float* Rg = ((g==0) ? Rz : (g==1) ? Ri : (g==2) ? Rf : Ro) + nh*DHH*DHH;
    float Rcol[64];
    #pragma unroll
    for (int d = 0; d < 64; d++) Rcol[d] = Rg[d*64 + e];

    const float* gb = (g==0) ? g_g0 : (g==1) ? g_g1 : (g==2) ? g_g2 : g_g3;
    const float* gp = gb + (size_t)(b*TT)*HH + nh*DHH + e;

    __shared__ __align__(16) float sh[64];
    __shared__ float spre[4][64];
    if (t < 64) sh[t] = 0.f;
    float c = 0.f, n = 0.f, m = 0.f;

    float pre = gp[0];          // prefetch step 0
    __syncthreads();

    for (int tt = 0; tt < TT; tt++) {
        // mat-vec with 4 independent accumulators (breaks the fma chain)
        float r0 = 0.f, r1 = 0.f, r2 = 0.f, r3 = 0.f;
        #pragma unroll
        for (int d4 = 0; d4 < 16; d4++) {
            float4 h4 = *(const float4*)&sh[d4*4];
            r0 = fmaf(h4.x, Rcol[d4*4+0], r0);
            r1 = fmaf(h4.y, Rcol[d4*4+1], r1);
            r2 = fmaf(h4.z, Rcol[d4*4+2], r2);
            r3 = fmaf(h4.w, Rcol[d4*4+3], r3);
        }
        spre[g][e] = pre + ((r0 + r1) + (r2 + r3));
        __syncthreads();                        // A: spre ready

        if (tt + 1 < TT) pre = gp[(size_t)(tt+1) * HH];   // prefetch

        if (t < 64) {
            float z   = tanhf(spre[0][e]);
            float ipp = spre[1][e];
            float fpp = spre[2][e];
            float o   = 1.f / (1.f + expf(-spre[3][e]));
            float mn  = fmaxf(fpp + m, ipp);
            float i_s = expf(ipp - mn);
            float f_s = expf(fpp + m - mn);
            m = mn;
            c = fmaf(f_s, c, i_s * z);
            n = fmaf(f_s, n, i_s);
            float h = o * c / n;
            sh[e] = h;
            g_h[(size_t)(b*TT + tt)*HH + nh*DHH + e] = h;
        }
        __syncthreads();                        // B: sh ready for next step
    }
}

// ---------------- head: out[b] = x[b,T-1,:] . fc_W + fc_b -------------------
__global__ void final_kernel(const float* __restrict__ fcW,
                             const float* __restrict__ fcb,
                             float* __restrict__ out) {
    int bI = blockIdx.x, t = threadIdx.x;
    float v = g_x[(size_t)(bI*TT + TT-1)*DD + t] * fcW[t];
    #pragma unroll
    for (int off = 16; off; off >>= 1)
        v += __shfl_xor_sync(0xffffffffu, v, off);
    __shared__ float a[8];
    if ((t & 31) == 0) a[t >> 5] = v;
    __syncthreads();
    if (t == 0) {
        float s = 0.f;
        #pragma unroll
        for (int i = 0; i < 8; i++) s += a[i];
        out[bI] = s + fcb[0];
    }
}

// ---------------- launch sequence -------------------------------------------
extern "C" void kernel_launch(void* const* d_in, const int* in_sizes, int n_in,
                              void* d_out, int out_size) {
    const float* X      = (const float*)d_in[0];
    const int*   dyad   = (const int*)  d_in[1];
    const float* embed  = (const float*)d_in[2];
    const float* m_ln_g = (const float*)d_in[3];
    const float* m_ln_b = (const float*)d_in[4];
    const float* m_Wq   = (const float*)d_in[5];
    const float* m_Wk   = (const float*)d_in[6];
    const float* m_Wv   = (const float*)d_in[7];
    const float* m_Wi   = (const float*)d_in[8];
    const float* m_Wf   = (const float*)d_in[9];
    const float* m_bi   = (const float*)d_in[10];
    const float* m_bf   = (const float*)d_in[11];
    const float* m_Wo   = (const float*)d_in[12];
    const float* m_Wp   = (const float*)d_in[13];
    const float* s_ln_g = (const float*)d_in[14];
    const float* s_ln_b = (const float*)d_in[15];
    const float* s_Wz   = (const float*)d_in[16];
    const float* s_Wi   = (const float*)d_in[17];
    const float* s_Wf   = (const float*)d_in[18];
    const float* s_Wo   = (const float*)d_in[19];
    const float* s_Rz   = (const float*)d_in[20];
    const float* s_Ri   = (const float*)d_in[21];
    const float* s_Rf   = (const float*)d_in[22];
    const float* s_Ro   = (const float*)d_in[23];
    const float* s_Wp   = (const float*)d_in[24];
    const float* fc_W   = (const float*)d_in[25];
    const float* fc_b   = (const float*)d_in[26];
    float* out = (float*)d_out;

    dim3 gGate(16, ROWS/GBM);   // (16, 64) fused 4-weight GEMM
    dim3 gRes (4,  ROWS/GBM);   // (4, 64)  Wp GEMM + residual

    build_x<<<ROWS, 256>>>(X, dyad, embed);

    // ---- mLSTM layer 0 ----
    ln_kernel<<<ROWS, 256>>>(m_ln_g, m_ln_b);
    gemm_gates<<<gGate, 256>>>(SEL_XN, m_Wq, m_Wk, m_Wv, m_Wo, 1);
    ipfp_kernel<<<(ROWS*NHH*2)/256, 256>>>(m_Wi, m_Wf, m_bi, m_bf);
    mlstm_scan<<<BB*NHH, 256>>>();
    gemm_res<<<gRes, 256>>>(SEL_H, m_Wp, SEL_X);

    // ---- sLSTM layer ----
    ln_kernel<<<ROWS, 256>>>(s_ln_g, s_ln_b);
    gemm_gates<<<gGate, 256>>>(SEL_XN, s_Wz, s_Wi, s_Wf, s_Wo, 0);
    slstm_scan<<<BB*NHH, 256>>>(s_Rz, s_Ri, s_Rf, s_Ro);
    gemm_res<<<gRes, 256>>>(SEL_H, s_Wp, SEL_X);

    // ---- mLSTM layer 1 ----
    ln_kernel<<<ROWS, 256>>>(m_ln_g + DD, m_ln_b + DD);
    gemm_gates<<<gGate, 256>>>(SEL_XN, m_Wq + DD*HH, m_Wk + DD*HH,
                               m_Wv + DD*HH, m_Wo + DD*HH, 1);
    ipfp_kernel<<<(ROWS*NHH*2)/256, 256>>>(m_Wi + DD*NHH, m_Wf + DD*NHH,
                                           m_bi + NHH, m_bf + NHH);
    mlstm_scan<<<BB*NHH, 256>>>();
    gemm_res<<<gRes, 256>>>(SEL_H, m_Wp + HH*DD, SEL_X);

    final_kernel<<<BB, 256>>>(fc_W, fc_b, out);
    (void)in_sizes; (void)n_in; (void)out_size;
}

// round 3
// speedup vs baseline: 1.8069x; 1.2394x over previous
#include <cuda_runtime.h>

// Problem constants
#define BB   32
#define TT   256
#define FF   224
#define EE   32
#define NHH  4
#define DHH  64
#define DD   256   // F + E
#define HH   256   // NH * DH
#define ROWS (BB*TT)   // 8192

// ---------------- scratch (static device globals; no allocation) ------------
__device__ float g_x [ROWS*DD];   // residual stream
__device__ float g_xn[ROWS*DD];   // layernorm output
__device__ float g_g0[ROWS*HH];   // q / z
__device__ float g_g1[ROWS*HH];   // k / i
__device__ float g_g2[ROWS*HH];   // v / f
__device__ float g_g3[ROWS*HH];   // o / o
__device__ float g_h [ROWS*HH];   // scan output
__device__ float g_ip[ROWS*NHH];
__device__ float g_fp[ROWS*NHH];
__device__ float g_bs[BB*NHH*TT]; // b_s = i_s - cumF_s
__device__ float g_Mt[BB*NHH*TT]; // running stabilizer max

__device__ __forceinline__ float* bufsel(int s) {
    switch (s) {
        case 0: return g_x;
        case 1: return g_xn;
        default: return g_h;
    }
}
#define SEL_X  0
#define SEL_XN 1
#define SEL_H  2

// ---------------- input assembly: concat(X, embed[dyad]) --------------------
__global__ void build_x(const float* __restrict__ X,
                        const int*   __restrict__ dyad,
                        const float* __restrict__ embed) {
    int row = blockIdx.x;
    int f   = threadIdx.x;
    int b   = row / TT;
    float v;
    if (f < FF) v = X[row*FF + f];
    else        v = embed[dyad[b]*EE + (f - FF)];
    g_x[row*DD + f] = v;
}

// ---------------- LayerNorm over last dim (256) ------------------------------
__global__ void ln_kernel(const float* __restrict__ gam,
                          const float* __restrict__ bet) {
    int row = blockIdx.x, t = threadIdx.x;
    float x  = g_x[row*DD + t];
    float s  = x, s2 = x*x;
    #pragma unroll
    for (int off = 16; off; off >>= 1) {
        s  += __shfl_xor_sync(0xffffffffu, s,  off);
        s2 += __shfl_xor_sync(0xffffffffu, s2, off);
    }
    __shared__ float a1[8], a2[8];
    __shared__ float smu, srs;
    if ((t & 31) == 0) { a1[t >> 5] = s; a2[t >> 5] = s2; }
    __syncthreads();
    if (t == 0) {
        float u = 0.f, u2 = 0.f;
        #pragma unroll
        for (int i = 0; i < 8; i++) { u += a1[i]; u2 += a2[i]; }
        float mu  = u  * (1.0f/DD);
        float var = u2 * (1.0f/DD) - mu*mu;
        smu = mu;
        srs = rsqrtf(var + 1e-5f);
    }
    __syncthreads();
    g_xn[row*DD + t] = (x - smu) * srs * gam[t] + bet[t];
}

// ---------------- shared 128x64 fp32 GEMM tile (GBK=16) ---------------------
#define GBM 128
#define GBN 64
#define GBK 16

__device__ __forceinline__ void gemm_tile128x64(const float* __restrict__ A,
                                                const float* __restrict__ Bw,
                                                int rowBase, int colBase,
                                                float (&acc)[8][4]) {
    const int K = DD, N = HH;
    __shared__ __align__(16) float As[GBK][GBM];
    __shared__ __align__(16) float Bs[GBK][GBN];
    int tid  = threadIdx.x;
    int aRow = tid >> 1,  aCol = (tid & 1) * 8;    // 128x16, 2 float4/thr
    int bRow = tid >> 4,  bCol = (tid & 15) * 4;   // 16x64,  1 float4/thr
    int tx = (tid & 15) * 4, ty = (tid >> 4) * 8;

    #pragma unroll
    for (int i = 0; i < 8; i++)
        #pragma unroll
        for (int j = 0; j < 4; j++) acc[i][j] = 0.f;

    const float* Aptr = A  + (size_t)(rowBase + aRow) * K + aCol;
    const float* Bptr = Bw + (size_t)bRow * N + colBase + bCol;

    float4 av0 = *(const float4*)Aptr;
    float4 av1 = *(const float4*)(Aptr + 4);
    float4 bv  = *(const float4*)Bptr;

    for (int k0 = 0; k0 < K; k0 += GBK) {
        As[aCol+0][aRow] = av0.x; As[aCol+1][aRow] = av0.y;
        As[aCol+2][aRow] = av0.z; As[aCol+3][aRow] = av0.w;
        As[aCol+4][aRow] = av1.x; As[aCol+5][aRow] = av1.y;
        As[aCol+6][aRow] = av1.z; As[aCol+7][aRow] = av1.w;
        *(float4*)&Bs[bRow][bCol] = bv;
        __syncthreads();

        if (k0 + GBK < K) {
            av0 = *(const float4*)(Aptr + k0 + GBK);
            av1 = *(const float4*)(Aptr + k0 + GBK + 4);
            bv  = *(const float4*)(Bptr + (size_t)(k0 + GBK) * N);
        }

        #pragma unroll
        for (int k = 0; k < GBK; k++) {
            float4 a0 = *(const float4*)&As[k][ty];
            float4 a1 = *(const float4*)&As[k][ty+4];
            float4 b0 = *(const float4*)&Bs[k][tx];
            float ar[8] = {a0.x,a0.y,a0.z,a0.w,a1.x,a1.y,a1.z,a1.w};
            float br[4] = {b0.x,b0.y,b0.z,b0.w};
            #pragma unroll
            for (int i = 0; i < 8; i++)
                #pragma unroll
                for (int j = 0; j < 4; j++)
                    acc[i][j] = fmaf(ar[i], br[j], acc[i][j]);
        }
        __syncthreads();
    }
}

// ---------------- fused 4-gate GEMM (one launch per layer) -------------------
__global__ void __launch_bounds__(256) gemm_gates(
    int aSel,
    const float* __restrict__ W0, const float* __restrict__ W1,
    const float* __restrict__ W2, const float* __restrict__ W3,
    int mTrans)
{
    int w       = blockIdx.x >> 2;
    int colBase = (blockIdx.x & 3) * GBN;
    int rowBase = blockIdx.y * GBM;
    const float* Bw = (w==0) ? W0 : (w==1) ? W1 : (w==2) ? W2 : W3;
    float*       C  = (w==0) ? g_g0 : (w==1) ? g_g1 : (w==2) ? g_g2 : g_g3;
    const float* A  = bufsel(aSel);

    float acc[8][4];
    gemm_tile128x64(A, Bw, rowBase, colBase, acc);

    int tx = (threadIdx.x & 15) * 4, ty = (threadIdx.x >> 4) * 8;
    #pragma unroll
    for (int i = 0; i < 8; i++) {
        float4 v = make_float4(acc[i][0], acc[i][1], acc[i][2], acc[i][3]);
        if (mTrans) {
            if (w == 1) { v.x *= 0.125f; v.y *= 0.125f; v.z *= 0.125f; v.w *= 0.125f; }
            else if (w == 3) {
                v.x = 1.f/(1.f+expf(-v.x)); v.y = 1.f/(1.f+expf(-v.y));
                v.z = 1.f/(1.f+expf(-v.z)); v.w = 1.f/(1.f+expf(-v.w));
            }
        }
        *(float4*)(C + (size_t)(rowBase + ty + i) * HH + colBase + tx) = v;
    }
}

// ---------------- single GEMM with residual accumulate (Wp) ------------------
__global__ void __launch_bounds__(256) gemm_res(
    int aSel, const float* __restrict__ Bw, int cSel)
{
    int colBase = blockIdx.x * GBN;
    int rowBase = blockIdx.y * GBM;
    const float* A = bufsel(aSel);
    float*       C = bufsel(cSel);

    float acc[8][4];
    gemm_tile128x64(A, Bw, rowBase, colBase, acc);

    int tx = (threadIdx.x & 15) * 4, ty = (threadIdx.x >> 4) * 8;
    #pragma unroll
    for (int i = 0; i < 8; i++) {
        float* Cp = C + (size_t)(rowBase + ty + i) * HH + colBase + tx;
        float4 c = *(const float4*)Cp;
        c.x += acc[i][0]; c.y += acc[i][1]; c.z += acc[i][2]; c.w += acc[i][3];
        *(float4*)Cp = c;
    }
}

// ---------------- mLSTM scalar gate preactivations (warp per row) -----------
__global__ void __launch_bounds__(256) ipfp_kernel(const float* __restrict__ Wi,
                                                   const float* __restrict__ Wf,
                                                   const float* __restrict__ bi,
                                                   const float* __restrict__ bf) {
    int w    = threadIdx.x >> 5;
    int lane = threadIdx.x & 31;
    int row  = blockIdx.x * 8 + w;
    const float* xr = g_xn + (size_t)row * DD;
    float acc[8] = {0,0,0,0,0,0,0,0};
    #pragma unroll
    for (int kk = 0; kk < 8; kk++) {
        int k = lane + kk*32;
        float x = xr[k];
        float4 wi = *(const float4*)&Wi[k*4];
        float4 wf = *(const float4*)&Wf[k*4];
        acc[0] = fmaf(x, wi.x, acc[0]); acc[1] = fmaf(x, wi.y, acc[1]);
        acc[2] = fmaf(x, wi.z, acc[2]); acc[3] = fmaf(x, wi.w, acc[3]);
        acc[4] = fmaf(x, wf.x, acc[4]); acc[5] = fmaf(x, wf.y, acc[5]);
        acc[6] = fmaf(x, wf.z, acc[6]); acc[7] = fmaf(x, wf.w, acc[7]);
    }
    #pragma unroll
    for (int g = 0; g < 8; g++)
        #pragma unroll
        for (int off = 16; off; off >>= 1)
            acc[g] += __shfl_xor_sync(0xffffffffu, acc[g], off);
    if (lane == 0) {
        #pragma unroll
        for (int h = 0; h < 4; h++) {
            g_ip[row*NHH + h] = acc[h]   + bi[h];
            g_fp[row*NHH + h] = acc[4+h] + bf[h];
        }
    }
}

// ---------------- mLSTM decay precompute: b_s, M_t (warp per (b,h)) ---------
// cumF_t = sum_{r<=t} fp_r (double), b_t = ip_t - cumF_t,
// M_t = max(0, max_{s<=t} b_s);  stabilized weight a_{t,s} = exp(b_s - M_t)
__global__ void mlstm_pre() {
    int bh   = blockIdx.x * 4 + (threadIdx.x >> 5);
    int lane = threadIdx.x & 31;
    int b = bh >> 2, nh = bh & 3;

    double fv[8], iv[8];
    #pragma unroll
    for (int i = 0; i < 8; i++) {
        int t = lane*8 + i;
        fv[i] = (double)g_fp[(size_t)(b*TT + t)*NHH + nh];
        iv[i] = (double)g_ip[(size_t)(b*TT + t)*NHH + nh];
    }
    // local inclusive cumsum
    double c = 0.0, loc[8];
    #pragma unroll
    for (int i = 0; i < 8; i++) { c += fv[i]; loc[i] = c; }
    // warp inclusive scan of chunk totals
    double v = c;
    #pragma unroll
    for (int off = 1; off < 32; off <<= 1) {
        double u = __shfl_up_sync(0xffffffffu, v, off);
        if (lane >= off) v += u;
    }
    double base = v - c;    // exclusive prefix for this lane's chunk
    double bt[8];
    #pragma unroll
    for (int i = 0; i < 8; i++) bt[i] = iv[i] - (base + loc[i]);
    // running max of b (with virtual 0 initial state)
    double mx = -1e300, lm[8];
    #pragma unroll
    for (int i = 0; i < 8; i++) { mx = mx > bt[i] ? mx : bt[i]; lm[i] = mx; }
    double mv = mx;
    #pragma unroll
    for (int off = 1; off < 32; off <<= 1) {
        double u = __shfl_up_sync(0xffffffffu, mv, off);
        if (lane >= off) mv = mv > u ? mv : u;
    }
    double exm = __shfl_up_sync(0xffffffffu, mv, 1);
    if (lane == 0) exm = -1e300;
    #pragma unroll
    for (int i = 0; i < 8; i++) {
        double Mi = lm[i] > exm ? lm[i] : exm;
        if (Mi < 0.0) Mi = 0.0;
        g_bs[bh*TT + lane*8 + i] = (float)bt[i];
        g_Mt[bh*TT + lane*8 + i] = (float)Mi;
    }
}

// ---------------- parallel mLSTM as causal weighted attention ---------------
// grid: (4 row-tiles, 128 bh). P[t][s] = (q_t . k_s) * exp(b_s - M_t), s<=t
// h_t = o_t * (P @ V)_t / max(|rowsum(P)_t|, 1)
__global__ void __launch_bounds__(256) mlstm_attn() {
    int rt = blockIdx.x;
    int bh = blockIdx.y;
    int b = bh >> 2, nh = bh & 3;
    int tid = threadIdx.x;
    int tx = tid & 15, ty = tid >> 4;
    int t0 = rt * 64;

    __shared__ __align__(16) float Qs[64][64];
    __shared__ __align__(16) float KS[64][64];   // K (xor-swizzled) then P (row-major)
    __shared__ __align__(16) float Vs[64][64];

    size_t rowBase = (size_t)(b*TT) * HH + nh*DHH;
    int lr = tid >> 4;            // 0..15
    int lc = (tid & 15) * 4;

    #pragma unroll
    for (int rr = 0; rr < 4; rr++) {
        int r = rr*16 + lr;
        *(float4*)&Qs[r][lc] = *(const float4*)&g_g0[rowBase + (size_t)(t0 + r)*HH + lc];
    }
    float Mreg[4];
    #pragma unroll
    for (int i = 0; i < 4; i++) Mreg[i] = g_Mt[bh*TT + t0 + ty*4 + i];

    float num[4][4];
    #pragma unroll
    for (int i = 0; i < 4; i++)
        #pragma unroll
        for (int j = 0; j < 4; j++) num[i][j] = 0.f;
    float dsp[4] = {0.f, 0.f, 0.f, 0.f};

    for (int jt = 0; jt <= rt; jt++) {
        int s0 = jt * 64;
        __syncthreads();        // prior-tile PV reads of KS/Vs complete
        #pragma unroll
        for (int rr = 0; rr < 4; rr++) {
            int r = rr*16 + lr;
            float4 kv = *(const float4*)&g_g1[rowBase + (size_t)(s0 + r)*HH + lc];
            int sc = lc ^ (((r >> 2) & 15) << 2);       // conflict-free swizzle
            *(float4*)&KS[r][sc] = kv;
            *(float4*)&Vs[r][lc] = *(const float4*)&g_g2[rowBase + (size_t)(s0 + r)*HH + lc];
        }
        __syncthreads();

        // scores: accS[i][j] = q_{t0+ty4+i} . k_{s0+tx4+j}
        float accS[4][4];
        #pragma unroll
        for (int i = 0; i < 4; i++)
            #pragma unroll
            for (int j = 0; j < 4; j++) accS[i][j] = 0.f;
        #pragma unroll
        for (int kc = 0; kc < 16; kc++) {
            float4 q4[4], k4[4];
            #pragma unroll
            for (int i = 0; i < 4; i++)
                q4[i] = *(const float4*)&Qs[ty*4 + i][kc*4];
            #pragma unroll
            for (int j = 0; j < 4; j++) {
                int s = tx*4 + j;
                int sc = (kc*4) ^ (((s >> 2) & 15) << 2);
                k4[j] = *(const float4*)&KS[s][sc];
            }
            #pragma unroll
            for (int i = 0; i < 4; i++)
                #pragma unroll
                for (int j = 0; j < 4; j++) {
                    accS[i][j] = fmaf(q4[i].x, k4[j].x, accS[i][j]);
                    accS[i][j] = fmaf(q4[i].y, k4[j].y, accS[i][j]);
                    accS[i][j] = fmaf(q4[i].z, k4[j].z, accS[i][j]);
                    accS[i][j] = fmaf(q4[i].w, k4[j].w, accS[i][j]);
                }
        }
        __syncthreads();        // KS reads done; safe to overwrite with P

        float bsv[4];
        #pragma unroll
        for (int j = 0; j < 4; j++) bsv[j] = g_bs[bh*TT + s0 + tx*4 + j];

        #pragma unroll
        for (int i = 0; i < 4; i++) {
            float4 Pr;
            float* pp = &Pr.x;
            #pragma unroll
            for (int j = 0; j < 4; j++) {
                float w = __expf(bsv[j] - Mreg[i]);
                if (jt == rt && (tx*4 + j) > (ty*4 + i)) w = 0.f;
                float p = accS[i][j] * w;
                pp[j] = p;
                dsp[i] += p;
            }
            *(float4*)&KS[ty*4 + i][tx*4] = Pr;    // P row-major
        }
        __syncthreads();

        // num += P @ V
        #pragma unroll
        for (int sc = 0; sc < 16; sc++) {
            float4 p4[4], vv[4];
            #pragma unroll
            for (int i = 0; i < 4; i++)
                p4[i] = *(const float4*)&KS[ty*4 + i][sc*4];
            #pragma unroll
            for (int ss = 0; ss < 4; ss++)
                vv[ss] = *(const float4*)&Vs[sc*4 + ss][tx*4];
            #pragma unroll
            for (int i = 0; i < 4; i++) {
                num[i][0] = fmaf(p4[i].x, vv[0].x, num[i][0]);
                num[i][1] = fmaf(p4[i].x, vv[0].y, num[i][1]);
                num[i][2] = fmaf(p4[i].x, vv[0].z, num[i][2]);
                num[i][3] = fmaf(p4[i].x, vv[0].w, num[i][3]);
                num[i][0] = fmaf(p4[i].y, vv[1].x, num[i][0]);
                num[i][1] = fmaf(p4[i].y, vv[1].y, num[i][1]);
                num[i][2] = fmaf(p4[i].y, vv[1].z, num[i][2]);
                num[i][3] = fmaf(p4[i].y, vv[1].w, num[i][3]);
                num[i][0] = fmaf(p4[i].z, vv[2].x, num[i][0]);
                num[i][1] = fmaf(p4[i].z, vv[2].y, num[i][1]);
                num[i][2] = fmaf(p4[i].z, vv[2].z, num[i][2]);
                num[i][3] = fmaf(p4[i].z, vv[2].w, num[i][3]);
                num[i][0] = fmaf(p4[i].w, vv[3].x, num[i][0]);
                num[i][1] = fmaf(p4[i].w, vv[3].y, num[i][1]);
                num[i][2] = fmaf(p4[i].w, vv[3].z, num[i][2]);
                num[i][3] = fmaf(p4[i].w, vv[3].w, num[i][3]);
            }
        }
    }

    // row-sum reduction across the 16 tx lanes (lane bits 0..3)
    #pragma unroll
    for (int i = 0; i < 4; i++) {
        #pragma unroll
        for (int off = 1; off < 16; off <<= 1)
            dsp[i] += __shfl_xor_sync(0xffffffffu, dsp[i], off);
    }
    #pragma unroll
    for (int i = 0; i < 4; i++) {
        float inv = 1.0f / fmaxf(fabsf(dsp[i]), 1.0f);
        int t = t0 + ty*4 + i;
        size_t addr = rowBase + (size_t)t*HH + tx*4;
        float4 o4 = *(const float4*)&g_g3[addr];
        float4 h4 = make_float4(num[i][0]*inv*o4.x, num[i][1]*inv*o4.y,
                                num[i][2]*inv*o4.z, num[i][3]*inv*o4.w);
        *(float4*)&g_h[addr] = h4;
    }
}

// ---------------- sLSTM recurrent scan (one block per (b,head)) -------------
__global__ void __launch_bounds__(256) slstm_scan(const float* __restrict__ Rz,
                                                  const float* __restrict__ Ri,
                                                  const float* __restrict__ Rf,
                                                  const float* __restrict__ Ro) {
    int b  = blockIdx.x >> 2;
    int nh = blockIdx.x & 3;
    int t  = threadIdx.x;
    int g  = t >> 6;
    int e  = t & 63;

    const float* Rg = ((g==0) ? Rz : (g==1) ? Ri : (g==2) ? Rf : Ro) + nh*DHH*DHH;
    float Rcol[64];
    #pragma unroll
    for (int d = 0; d < 64; d++) Rcol[d] = Rg[d*64 + e];

    const float* gb = (g==0) ? g_g0 : (g==1) ? g_g1 : (g==2) ? g_g2 : g_g3;
    const float* gp = gb + (size_t)(b*TT)*HH + nh*DHH + e;

    __shared__ __align__(16) float sh[64];
    __shared__ float spre[4][64];
    if (t < 64) sh[t] = 0.f;
    float c = 0.f, n = 0.f, m = 0.f;

    float pre = gp[0];
    __syncthreads();

    for (int tt = 0; tt < TT; tt++) {
        float r0 = 0.f, r1 = 0.f, r2 = 0.f, r3 = 0.f;
        #pragma unroll
        for (int d4 = 0; d4 < 16; d4++) {
            float4 h4 = *(const float4*)&sh[d4*4];
            r0 = fmaf(h4.x, Rcol[d4*4+0], r0);
            r1 = fmaf(h4.y, Rcol[d4*4+1], r1);
            r2 = fmaf(h4.z, Rcol[d4*4+2], r2);
            r3 = fmaf(h4.w, Rcol[d4*4+3], r3);
        }
        spre[g][e] = pre + ((r0 + r1) + (r2 + r3));
        __syncthreads();

        if (tt + 1 < TT) pre = gp[(size_t)(tt+1) * HH];

        if (t < 64) {
            float z   = tanhf(spre[0][e]);
            float ipp = spre[1][e];
            float fpp = spre[2][e];
            float o   = 1.f / (1.f + expf(-spre[3][e]));
            float mn  = fmaxf(fpp + m, ipp);
            float i_s = expf(ipp - mn);
            float f_s = expf(fpp + m - mn);
            m = mn;
            c = fmaf(f_s, c, i_s * z);
            n = fmaf(f_s, n, i_s);
            float h = o * c / n;
            sh[e] = h;
            g_h[(size_t)(b*TT + tt)*HH + nh*DHH + e] = h;
        }
        __syncthreads();
    }
}

// ---------------- head: out[b] = x[b,T-1,:] . fc_W + fc_b -------------------
__global__ void final_kernel(const float* __restrict__ fcW,
                             const float* __restrict__ fcb,
                             float* __restrict__ out) {
    int bI = blockIdx.x, t = threadIdx.x;
    float v = g_x[(size_t)(bI*TT + TT-1)*DD + t] * fcW[t];
    #pragma unroll
    for (int off = 16; off; off >>= 1)
        v += __shfl_xor_sync(0xffffffffu, v, off);
    __shared__ float a[8];
    if ((t & 31) == 0) a[t >> 5] = v;
    __syncthreads();
    if (t == 0) {
        float s = 0.f;
        #pragma unroll
        for (int i = 0; i < 8; i++) s += a[i];
        out[bI] = s + fcb[0];
    }
}

// ---------------- launch sequence -------------------------------------------
extern "C" void kernel_launch(void* const* d_in, const int* in_sizes, int n_in,
                              void* d_out, int out_size) {
    const float* X      = (const float*)d_in[0];
    const int*   dyad   = (const int*)  d_in[1];
    const float* embed  = (const float*)d_in[2];
    const float* m_ln_g = (const float*)d_in[3];
    const float* m_ln_b = (const float*)d_in[4];
    const float* m_Wq   = (const float*)d_in[5];
    const float* m_Wk   = (const float*)d_in[6];
    const float* m_Wv   = (const float*)d_in[7];
    const float* m_Wi   = (const float*)d_in[8];
    const float* m_Wf   = (const float*)d_in[9];
    const float* m_bi   = (const float*)d_in[10];
    const float* m_bf   = (const float*)d_in[11];
    const float* m_Wo   = (const float*)d_in[12];
    const float* m_Wp   = (const float*)d_in[13];
    const float* s_ln_g = (const float*)d_in[14];
    const float* s_ln_b = (const float*)d_in[15];
    const float* s_Wz   = (const float*)d_in[16];
    const float* s_Wi   = (const float*)d_in[17];
    const float* s_Wf   = (const float*)d_in[18];
    const float* s_Wo   = (const float*)d_in[19];
    const float* s_Rz   = (const float*)d_in[20];
    const float* s_Ri   = (const float*)d_in[21];
    const float* s_Rf   = (const float*)d_in[22];
    const float* s_Ro   = (const float*)d_in[23];
    const float* s_Wp   = (const float*)d_in[24];
    const float* fc_W   = (const float*)d_in[25];
    const float* fc_b   = (const float*)d_in[26];
    float* out = (float*)d_out;

    dim3 gGate(16, ROWS/GBM);   // (16, 64) fused 4-weight GEMM
    dim3 gRes (4,  ROWS/GBM);   // (4, 64)
    dim3 gAttn(4, BB*NHH);      // (4 row-tiles, 128 bh)

    build_x<<<ROWS, 256>>>(X, dyad, embed);

    // ---- mLSTM layer 0 ----
    ln_kernel<<<ROWS, 256>>>(m_ln_g, m_ln_b);
    gemm_gates<<<gGate, 256>>>(SEL_XN, m_Wq, m_Wk, m_Wv, m_Wo, 1);
    ipfp_kernel<<<ROWS/8, 256>>>(m_Wi, m_Wf, m_bi, m_bf);
    mlstm_pre<<<BB*NHH/4, 128>>>();
    mlstm_attn<<<gAttn, 256>>>();
    gemm_res<<<gRes, 256>>>(SEL_H, m_Wp, SEL_X);

    // ---- sLSTM layer ----
    ln_kernel<<<ROWS, 256>>>(s_ln_g, s_ln_b);
    gemm_gates<<<gGate, 256>>>(SEL_XN, s_Wz, s_Wi, s_Wf, s_Wo, 0);
    slstm_scan<<<BB*NHH, 256>>>(s_Rz, s_Ri, s_Rf, s_Ro);
    gemm_res<<<gRes, 256>>>(SEL_H, s_Wp, SEL_X);

    // ---- mLSTM layer 1 ----
    ln_kernel<<<ROWS, 256>>>(m_ln_g + DD, m_ln_b + DD);
    gemm_gates<<<gGate, 256>>>(SEL_XN, m_Wq + DD*HH, m_Wk + DD*HH,
                               m_Wv + DD*HH, m_Wo + DD*HH, 1);
    ipfp_kernel<<<ROWS/8, 256>>>(m_Wi + DD*NHH, m_Wf + DD*NHH,
                                 m_bi + NHH, m_bf + NHH);
    mlstm_pre<<<BB*NHH/4, 128>>>();
    mlstm_attn<<<gAttn, 256>>>();
    gemm_res<<<gRes, 256>>>(SEL_H, m_Wp + HH*DD, SEL_X);

    final_kernel<<<BB, 256>>>(fc_W, fc_b, out);
    (void)in_sizes; (void)n_in; (void)out_size;
}

// round 5
// speedup vs baseline: 2.3410x; 1.2956x over previous
#include <cuda_runtime.h>
#include <cstdint>

// Problem constants
#define BB   32
#define TT   256
#define FF   224
#define EE   32
#define NHH  4
#define DHH  64
#define DD   256
#define HH   256
#define ROWS (BB*TT)   // 8192

// ---------------- scratch (static device globals; no allocation) ------------
__device__ float g_x [ROWS*DD];
__device__ float g_xn[ROWS*DD];
__device__ float g_g0[ROWS*HH];
__device__ float g_g1[ROWS*HH];
__device__ float g_g2[ROWS*HH];
__device__ float g_g3[ROWS*HH];
__device__ float g_h [ROWS*HH];
__device__ float g_ip[ROWS*NHH];
__device__ float g_fp[ROWS*NHH];
__device__ float g_bs[BB*NHH*TT];
__device__ float g_Mt[BB*NHH*TT];

__device__ __forceinline__ float* bufsel(int s) {
    switch (s) {
        case 0: return g_x;
        case 1: return g_xn;
        default: return g_h;
    }
}
#define SEL_X  0
#define SEL_XN 1
#define SEL_H  2

__device__ __forceinline__ uint32_t to_tf32(float x) {
    uint32_t u;
    asm("cvt.rna.tf32.f32 %0, %1;" : "=r"(u) : "f"(x));
    return u;
}

// ---------------- input assembly ---------------------------------------------
__global__ void build_x(const float* __restrict__ X,
                        const int*   __restrict__ dyad,
                        const float* __restrict__ embed) {
    int row = blockIdx.x;
    int f   = threadIdx.x;
    int b   = row / TT;
    float v;
    if (f < FF) v = X[row*FF + f];
    else        v = embed[dyad[b]*EE + (f - FF)];
    g_x[row*DD + f] = v;
}

// ---------------- LayerNorm --------------------------------------------------
__global__ void ln_kernel(const float* __restrict__ gam,
                          const float* __restrict__ bet) {
    int row = blockIdx.x, t = threadIdx.x;
    float x  = g_x[row*DD + t];
    float s  = x, s2 = x*x;
    #pragma unroll
    for (int off = 16; off; off >>= 1) {
        s  += __shfl_xor_sync(0xffffffffu, s,  off);
        s2 += __shfl_xor_sync(0xffffffffu, s2, off);
    }
    __shared__ float a1[8], a2[8];
    __shared__ float smu, srs;
    if ((t & 31) == 0) { a1[t >> 5] = s; a2[t >> 5] = s2; }
    __syncthreads();
    if (t == 0) {
        float u = 0.f, u2 = 0.f;
        #pragma unroll
        for (int i = 0; i < 8; i++) { u += a1[i]; u2 += a2[i]; }
        float mu  = u  * (1.0f/DD);
        float var = u2 * (1.0f/DD) - mu*mu;
        smu = mu;
        srs = rsqrtf(var + 1e-5f);
    }
    __syncthreads();
    g_xn[row*DD + t] = (x - smu) * srs * gam[t] + bet[t];
}

// ---------------- tf32 mma.sync GEMM: 128x128 tile, 8 warps ------------------
// C[8192,256] = A[8192,256] @ W[256,256]   (W is K-major [k][n] as given)
// mode 0: mLSTM gates (w==1 scale 0.125, w==3 sigmoid)
// mode 1: sLSTM gates
// mode 2: Wp @ h + residual accumulate into g_x (W0 = Wp)
#define ASTRIDE 20
#define BSTRIDE 136

__device__ __forceinline__ void mma_tf32(float (&d)[4],
                                         const uint32_t (&a)[4],
                                         const uint32_t (&b)[2]) {
    asm volatile(
        "mma.sync.aligned.m16n8k8.row.col.f32.tf32.tf32.f32 "
        "{%0,%1,%2,%3}, {%4,%5,%6,%7}, {%8,%9}, {%0,%1,%2,%3};"
        : "+f"(d[0]), "+f"(d[1]), "+f"(d[2]), "+f"(d[3])
        : "r"(a[0]), "r"(a[1]), "r"(a[2]), "r"(a[3]),
          "r"(b[0]), "r"(b[1]));
}

__global__ void __launch_bounds__(256, 1) gemm_mma(
    int aSel,
    const float* __restrict__ W0, const float* __restrict__ W1,
    const float* __restrict__ W2, const float* __restrict__ W3,
    int mode)
{
    __shared__ uint32_t As[128][ASTRIDE];   // [m][k], tf32 bits
    __shared__ uint32_t Bs[16][BSTRIDE];    // [k][n], tf32 bits

    int tid  = threadIdx.x;
    int wid  = tid >> 5;
    int lane = tid & 31;
    int grp  = lane >> 2;     // 0..7
    int tig  = lane & 3;      // 0..3

    int w, nt;
    if (mode == 2) { w = 0; nt = blockIdx.x; }
    else           { w = blockIdx.x >> 1; nt = blockIdx.x & 1; }
    int colBase = nt * 128;
    int rowBase = blockIdx.y * 128;
    const float* Wsel = (w==0) ? W0 : (w==1) ? W1 : (w==2) ? W2 : W3;
    const float* A    = bufsel(aSel) + (size_t)rowBase * DD;

    int warpM = wid >> 1;     // 0..3  -> 32-row slab
    int warpN = wid & 1;      // 0..1  -> 64-col slab

    float acc[2][8][4];
    #pragma unroll
    for (int i = 0; i < 2; i++)
        #pragma unroll
        for (int j = 0; j < 8; j++)
            #pragma unroll
            for (int q = 0; q < 4; q++) acc[i][j][q] = 0.f;

    // global staging: A 128x16 (2 float4/thr), B 16x128 (2 float4/thr)
    int aRow = tid >> 1,  aCol = (tid & 1) * 8;
    int bRow = tid >> 4,  bCol = (tid & 15) * 8;
    const float* Aptr = A    + (size_t)aRow * DD + aCol;
    const float* Bptr = Wsel + (size_t)bRow * HH + colBase + bCol;

    float4 av0 = *(const float4*)Aptr;
    float4 av1 = *(const float4*)(Aptr + 4);
    float4 bv0 = *(const float4*)Bptr;
    float4 bv1 = *(const float4*)(Bptr + 4);

    for (int k0 = 0; k0 < DD; k0 += 16) {
        As[aRow][aCol+0] = to_tf32(av0.x); As[aRow][aCol+1] = to_tf32(av0.y);
        As[aRow][aCol+2] = to_tf32(av0.z); As[aRow][aCol+3] = to_tf32(av0.w);
        As[aRow][aCol+4] = to_tf32(av1.x); As[aRow][aCol+5] = to_tf32(av1.y);
        As[aRow][aCol+6] = to_tf32(av1.z); As[aRow][aCol+7] = to_tf32(av1.w);
        Bs[bRow][bCol+0] = to_tf32(bv0.x); Bs[bRow][bCol+1] = to_tf32(bv0.y);
        Bs[bRow][bCol+2] = to_tf32(bv0.z); Bs[bRow][bCol+3] = to_tf32(bv0.w);
        Bs[bRow][bCol+4] = to_tf32(bv1.x); Bs[bRow][bCol+5] = to_tf32(bv1.y);
        Bs[bRow][bCol+6] = to_tf32(bv1.z); Bs[bRow][bCol+7] = to_tf32(bv1.w);
        __syncthreads();

        if (k0 + 16 < DD) {
            av0 = *(const float4*)(Aptr + k0 + 16);
            av1 = *(const float4*)(Aptr + k0 + 20);
            bv0 = *(const float4*)(Bptr + (size_t)(k0 + 16) * HH);
            bv1 = *(const float4*)(Bptr + (size_t)(k0 + 16) * HH + 4);
        }

        #pragma unroll
        for (int ks = 0; ks < 2; ks++) {
            uint32_t afr[2][4];
            #pragma unroll
            for (int mt = 0; mt < 2; mt++) {
                int r = warpM*32 + mt*16 + grp;
                int c = ks*8 + tig;
                afr[mt][0] = As[r][c];
                afr[mt][1] = As[r+8][c];
                afr[mt][2] = As[r][c+4];
                afr[mt][3] = As[r+8][c+4];
            }
            uint32_t bfr[8][2];
            #pragma unroll
            for (int nt2 = 0; nt2 < 8; nt2++) {
                int c = warpN*64 + nt2*8 + grp;
                bfr[nt2][0] = Bs[ks*8 + tig][c];
                bfr[nt2][1] = Bs[ks*8 + tig + 4][c];
            }
            #pragma unroll
            for (int mt = 0; mt < 2; mt++)
                #pragma unroll
                for (int nt2 = 0; nt2 < 8; nt2++)
                    mma_tf32(acc[mt][nt2], afr[mt], bfr[nt2]);
        }
        __syncthreads();
    }

    // epilogue
    float* C = (mode == 2) ? g_x
             : (w == 0) ? g_g0 : (w == 1) ? g_g1 : (w == 2) ? g_g2 : g_g3;
    bool scaleK = (mode == 0) && (w == 1);
    bool sig    = (mode == 0) && (w == 3);

    #pragma unroll
    for (int mt = 0; mt < 2; mt++) {
        #pragma unroll
        for (int nt2 = 0; nt2 < 8; nt2++) {
            float v[4] = {acc[mt][nt2][0], acc[mt][nt2][1],
                          acc[mt][nt2][2], acc[mt][nt2][3]};
            if (scaleK) {
                #pragma unroll
                for (int q = 0; q < 4; q++) v[q] *= 0.125f;
            } else if (sig) {
                #pragma unroll
                for (int q = 0; q < 4; q++) v[q] = 1.f/(1.f+expf(-v[q]));
            }
            int r0 = rowBase + warpM*32 + mt*16 + grp;
            int c0 = colBase + warpN*64 + nt2*8 + tig*2;
            float* p0 = C + (size_t)r0 * HH + c0;
            float* p1 = C + (size_t)(r0 + 8) * HH + c0;
            if (mode == 2) {
                float2 o0 = *(const float2*)p0;
                float2 o1 = *(const float2*)p1;
                o0.x += v[0]; o0.y += v[1];
                o1.x += v[2]; o1.y += v[3];
                *(float2*)p0 = o0;
                *(float2*)p1 = o1;
            } else {
                *(float2*)p0 = make_float2(v[0], v[1]);
                *(float2*)p1 = make_float2(v[2], v[3]);
            }
        }
    }
}

// ---------------- mLSTM scalar gate preactivations --------------------------
__global__ void __launch_bounds__(256) ipfp_kernel(const float* __restrict__ Wi,
                                                   const float* __restrict__ Wf,
                                                   const float* __restrict__ bi,
                                                   const float* __restrict__ bf) {
    int w    = threadIdx.x >> 5;
    int lane = threadIdx.x & 31;
    int row  = blockIdx.x * 8 + w;
    const float* xr = g_xn + (size_t)row * DD;
    float acc[8] = {0,0,0,0,0,0,0,0};
    #pragma unroll
    for (int kk = 0; kk < 8; kk++) {
        int k = lane + kk*32;
        float x = xr[k];
        float4 wi = *(const float4*)&Wi[k*4];
        float4 wf = *(const float4*)&Wf[k*4];
        acc[0] = fmaf(x, wi.x, acc[0]); acc[1] = fmaf(x, wi.y, acc[1]);
        acc[2] = fmaf(x, wi.z, acc[2]); acc[3] = fmaf(x, wi.w, acc[3]);
        acc[4] = fmaf(x, wf.x, acc[4]); acc[5] = fmaf(x, wf.y, acc[5]);
        acc[6] = fmaf(x, wf.z, acc[6]); acc[7] = fmaf(x, wf.w, acc[7]);
    }
    #pragma unroll
    for (int g = 0; g < 8; g++)
        #pragma unroll
        for (int off = 16; off; off >>= 1)
            acc[g] += __shfl_xor_sync(0xffffffffu, acc[g], off);
    if (lane == 0) {
        #pragma unroll
        for (int h = 0; h < 4; h++) {
            g_ip[row*NHH + h] = acc[h]   + bi[h];
            g_fp[row*NHH + h] = acc[4+h] + bf[h];
        }
    }
}

// ---------------- mLSTM decay precompute ------------------------------------
__global__ void mlstm_pre() {
    int bh   = blockIdx.x * 4 + (threadIdx.x >> 5);
    int lane = threadIdx.x & 31;
    int b = bh >> 2, nh = bh & 3;

    double fv[8], iv[8];
    #pragma unroll
    for (int i = 0; i < 8; i++) {
        int t = lane*8 + i;
        fv[i] = (double)g_fp[(size_t)(b*TT + t)*NHH + nh];
        iv[i] = (double)g_ip[(size_t)(b*TT + t)*NHH + nh];
    }
    double c = 0.0, loc[8];
    #pragma unroll
    for (int i = 0; i < 8; i++) { c += fv[i]; loc[i] = c; }
    double v = c;
    #pragma unroll
    for (int off = 1; off < 32; off <<= 1) {
        double u = __shfl_up_sync(0xffffffffu, v, off);
        if (lane >= off) v += u;
    }
    double base = v - c;
    double bt[8];
    #pragma unroll
    for (int i = 0; i < 8; i++) bt[i] = iv[i] - (base + loc[i]);
    double mx = -1e300, lm[8];
    #pragma unroll
    for (int i = 0; i < 8; i++) { mx = mx > bt[i] ? mx : bt[i]; lm[i] = mx; }
    double mv = mx;
    #pragma unroll
    for (int off = 1; off < 32; off <<= 1) {
        double u = __shfl_up_sync(0xffffffffu, mv, off);
        if (lane >= off) mv = mv > u ? mv : u;
    }
    double exm = __shfl_up_sync(0xffffffffu, mv, 1);
    if (lane == 0) exm = -1e300;
    #pragma unroll
    for (int i = 0; i < 8; i++) {
        double Mi = lm[i] > exm ? lm[i] : exm;
        if (Mi < 0.0) Mi = 0.0;
        g_bs[bh*TT + lane*8 + i] = (float)bt[i];
        g_Mt[bh*TT + lane*8 + i] = (float)Mi;
    }
}

// ---------------- parallel mLSTM (causal weighted attention) ----------------
__global__ void __launch_bounds__(256) mlstm_attn() {
    int rt = blockIdx.x;
    int bh = blockIdx.y;
    int b = bh >> 2, nh = bh & 3;
    int tid = threadIdx.x;
    int tx = tid & 15, ty = tid >> 4;
    int t0 = rt * 64;

    __shared__ __align__(16) float Qs[64][64];
    __shared__ __align__(16) float KS[64][64];
    __shared__ __align__(16) float Vs[64][64];

    size_t rowBase = (size_t)(b*TT) * HH + nh*DHH;
    int lr = tid >> 4;
    int lc = (tid & 15) * 4;

    #pragma unroll
    for (int rr = 0; rr < 4; rr++) {
        int r = rr*16 + lr;
        *(float4*)&Qs[r][lc] = *(const float4*)&g_g0[rowBase + (size_t)(t0 + r)*HH + lc];
    }
    float Mreg[4];
    #pragma unroll
    for (int i = 0; i < 4; i++) Mreg[i] = g_Mt[bh*TT + t0 + ty*4 + i];

    float num[4][4];
    #pragma unroll
    for (int i = 0; i < 4; i++)
        #pragma unroll
        for (int j = 0; j < 4; j++) num[i][j] = 0.f;
    float dsp[4] = {0.f, 0.f, 0.f, 0.f};

    for (int jt = 0; jt <= rt; jt++) {
        int s0 = jt * 64;
        __syncthreads();
        #pragma unroll
        for (int rr = 0; rr < 4; rr++) {
            int r = rr*16 + lr;
            float4 kv = *(const float4*)&g_g1[rowBase + (size_t)(s0 + r)*HH + lc];
            int sc = lc ^ (((r >> 2) & 15) << 2);
            *(float4*)&KS[r][sc] = kv;
            *(float4*)&Vs[r][lc] = *(const float4*)&g_g2[rowBase + (size_t)(s0 + r)*HH + lc];
        }
        __syncthreads();

        float accS[4][4];
        #pragma unroll
        for (int i = 0; i < 4; i++)
            #pragma unroll
            for (int j = 0; j < 4; j++) accS[i][j] = 0.f;
        #pragma unroll
        for (int kc = 0; kc < 16; kc++) {
            float4 q4[4], k4[4];
            #pragma unroll
            for (int i = 0; i < 4; i++)
                q4[i] = *(const float4*)&Qs[ty*4 + i][kc*4];
            #pragma unroll
            for (int j = 0; j < 4; j++) {
                int s = tx*4 + j;
                int sc = (kc*4) ^ (((s >> 2) & 15) << 2);
                k4[j] = *(const float4*)&KS[s][sc];
            }
            #pragma unroll
            for (int i = 0; i < 4; i++)
                #pragma unroll
                for (int j = 0; j < 4; j++) {
                    accS[i][j] = fmaf(q4[i].x, k4[j].x, accS[i][j]);
                    accS[i][j] = fmaf(q4[i].y, k4[j].y, accS[i][j]);
                    accS[i][j] = fmaf(q4[i].z, k4[j].z, accS[i][j]);
                    accS[i][j] = fmaf(q4[i].w, k4[j].w, accS[i][j]);
                }
        }
        __syncthreads();

        float bsv[4];
        #pragma unroll
        for (int j = 0; j < 4; j++) bsv[j] = g_bs[bh*TT + s0 + tx*4 + j];

        #pragma unroll
        for (int i = 0; i < 4; i++) {
            float4 Pr;
            float* pp = &Pr.x;
            #pragma unroll
            for (int j = 0; j < 4; j++) {
                float w = __expf(bsv[j] - Mreg[i]);
                if (jt == rt && (tx*4 + j) > (ty*4 + i)) w = 0.f;
                float p = accS[i][j] * w;
                pp[j] = p;
                dsp[i] += p;
            }
            *(float4*)&KS[ty*4 + i][tx*4] = Pr;
        }
        __syncthreads();

        #pragma unroll
        for (int sc = 0; sc < 16; sc++) {
            float4 p4[4], vv[4];
            #pragma unroll
            for (int i = 0; i < 4; i++)
                p4[i] = *(const float4*)&KS[ty*4 + i][sc*4];
            #pragma unroll
            for (int ss = 0; ss < 4; ss++)
                vv[ss] = *(const float4*)&Vs[sc*4 + ss][tx*4];
            #pragma unroll
            for (int i = 0; i < 4; i++) {
                num[i][0] = fmaf(p4[i].x, vv[0].x, num[i][0]);
                num[i][1] = fmaf(p4[i].x, vv[0].y, num[i][1]);
                num[i][2] = fmaf(p4[i].x, vv[0].z, num[i][2]);
                num[i][3] = fmaf(p4[i].x, vv[0].w, num[i][3]);
                num[i][0] = fmaf(p4[i].y, vv[1].x, num[i][0]);
                num[i][1] = fmaf(p4[i].y, vv[1].y, num[i][1]);
                num[i][2] = fmaf(p4[i].y, vv[1].z, num[i][2]);
                num[i][3] = fmaf(p4[i].y, vv[1].w, num[i][3]);
                num[i][0] = fmaf(p4[i].z, vv[2].x, num[i][0]);
                num[i][1] = fmaf(p4[i].z, vv[2].y, num[i][1]);
                num[i][2] = fmaf(p4[i].z, vv[2].z, num[i][2]);
                num[i][3] = fmaf(p4[i].z, vv[2].w, num[i][3]);
                num[i][0] = fmaf(p4[i].w, vv[3].x, num[i][0]);
                num[i][1] = fmaf(p4[i].w, vv[3].y, num[i][1]);
                num[i][2] = fmaf(p4[i].w, vv[3].z, num[i][2]);
                num[i][3] = fmaf(p4[i].w, vv[3].w, num[i][3]);
            }
        }
    }

    #pragma unroll
    for (int i = 0; i < 4; i++) {
        #pragma unroll
        for (int off = 1; off < 16; off <<= 1)
            dsp[i] += __shfl_xor_sync(0xffffffffu, dsp[i], off);
    }
    #pragma unroll
    for (int i = 0; i < 4; i++) {
        float inv = 1.0f / fmaxf(fabsf(dsp[i]), 1.0f);
        int t = t0 + ty*4 + i;
        size_t addr = rowBase + (size_t)t*HH + tx*4;
        float4 o4 = *(const float4*)&g_g3[addr];
        float4 h4 = make_float4(num[i][0]*inv*o4.x, num[i][1]*inv*o4.y,
                                num[i][2]*inv*o4.z, num[i][3]*inv*o4.w);
        *(float4*)&g_h[addr] = h4;
    }
}

// ---------------- sLSTM recurrent scan --------------------------------------
__global__ void __launch_bounds__(256) slstm_scan(const float* __restrict__ Rz,
                                                  const float* __restrict__ Ri,
                                                  const float* __restrict__ Rf,
                                                  const float* __restrict__ Ro) {
    int b  = blockIdx.x >> 2;
    int nh = blockIdx.x & 3;
    int t  = threadIdx.x;
    int g  = t >> 6;
    int e  = t & 63;

    const float* Rg = ((g==0) ? Rz : (g==1) ? Ri : (g==2) ? Rf : Ro) + nh*DHH*DHH;
    float Rcol[64];
    #pragma unroll
    for (int d = 0; d < 64; d++) Rcol[d] = Rg[d*64 + e];

    const float* gb = (g==0) ? g_g0 : (g==1) ? g_g1 : (g==2) ? g_g2 : g_g3;
    const float* gp = gb + (size_t)(b*TT)*HH + nh*DHH + e;

    __shared__ __align__(16) float sh[64];
    __shared__ float spre[4][64];
    if (t < 64) sh[t] = 0.f;
    float c = 0.f, n = 0.f, m = 0.f;

    float pre = gp[0];
    __syncthreads();

    for (int tt = 0; tt < TT; tt++) {
        float r0 = 0.f, r1 = 0.f, r2 = 0.f, r3 = 0.f;
        #pragma unroll
        for (int d4 = 0; d4 < 16; d4++) {
            float4 h4 = *(const float4*)&sh[d4*4];
            r0 = fmaf(h4.x, Rcol[d4*4+0], r0);
            r1 = fmaf(h4.y, Rcol[d4*4+1], r1);
            r2 = fmaf(h4.z, Rcol[d4*4+2], r2);
            r3 = fmaf(h4.w, Rcol[d4*4+3], r3);
        }
        float p = pre + ((r0 + r1) + (r2 + r3));
        if (g == 0) p = tanhf(p);
        else if (g == 3) p = 1.f / (1.f + expf(-p));
        spre[g][e] = p;
        __syncthreads();

        if (tt + 1 < TT) pre = gp[(size_t)(tt+1) * HH];

        if (t < 64) {
            float z   = spre[0][e];
            float ipp = spre[1][e];
            float fpp = spre[2][e];
            float o   = spre[3][e];
            float mn  = fmaxf(fpp + m, ipp);
            float i_s = expf(ipp - mn);
            float f_s = expf(fpp + m - mn);
            m = mn;
            c = fmaf(f_s, c, i_s * z);
            n = fmaf(f_s, n, i_s);
            float h = o * c / n;
            sh[e] = h;
            g_h[(size_t)(b*TT + tt)*HH + nh*DHH + e] = h;
        }
        __syncthreads();
    }
}

// ---------------- head --------------------------------------------------------
__global__ void final_kernel(const float* __restrict__ fcW,
                             const float* __restrict__ fcb,
                             float* __restrict__ out) {
    int bI = blockIdx.x, t = threadIdx.x;
    float v = g_x[(size_t)(bI*TT + TT-1)*DD + t] * fcW[t];
    #pragma unroll
    for (int off = 16; off; off >>= 1)
        v += __shfl_xor_sync(0xffffffffu, v, off);
    __shared__ float a[8];
    if ((t & 31) == 0) a[t >> 5] = v;
    __syncthreads();
    if (t == 0) {
        float s = 0.f;
        #pragma unroll
        for (int i = 0; i < 8; i++) s += a[i];
        out[bI] = s + fcb[0];
    }
}

// ---------------- launch sequence --------------------------------------------
extern "C" void kernel_launch(void* const* d_in, const int* in_sizes, int n_in,
                              void* d_out, int out_size) {
    const float* X      = (const float*)d_in[0];
    const int*   dyad   = (const int*)  d_in[1];
    const float* embed  = (const float*)d_in[2];
    const float* m_ln_g = (const float*)d_in[3];
    const float* m_ln_b = (const float*)d_in[4];
    const float* m_Wq   = (const float*)d_in[5];
    const float* m_Wk   = (const float*)d_in[6];
    const float* m_Wv   = (const float*)d_in[7];
    const float* m_Wi   = (const float*)d_in[8];
    const float* m_Wf   = (const float*)d_in[9];
    const float* m_bi   = (const float*)d_in[10];
    const float* m_bf   = (const float*)d_in[11];
    const float* m_Wo   = (const float*)d_in[12];
    const float* m_Wp   = (const float*)d_in[13];
    const float* s_ln_g = (const float*)d_in[14];
    const float* s_ln_b = (const float*)d_in[15];
    const float* s_Wz   = (const float*)d_in[16];
    const float* s_Wi   = (const float*)d_in[17];
    const float* s_Wf   = (const float*)d_in[18];
    const float* s_Wo   = (const float*)d_in[19];
    const float* s_Rz   = (const float*)d_in[20];
    const float* s_Ri   = (const float*)d_in[21];
    const float* s_Rf   = (const float*)d_in[22];
    const float* s_Ro   = (const float*)d_in[23];
    const float* s_Wp   = (const float*)d_in[24];
    const float* fc_W   = (const float*)d_in[25];
    const float* fc_b   = (const float*)d_in[26];
    float* out = (float*)d_out;

    dim3 gGate(8, ROWS/128);   // 4 weights x 2 col tiles, 64 row tiles
    dim3 gRes (2, ROWS/128);
    dim3 gAttn(4, BB*NHH);

    build_x<<<ROWS, 256>>>(X, dyad, embed);

    // ---- mLSTM layer 0 ----
    ln_kernel<<<ROWS, 256>>>(m_ln_g, m_ln_b);
    gemm_mma<<<gGate, 256>>>(SEL_XN, m_Wq, m_Wk, m_Wv, m_Wo, 0);
    ipfp_kernel<<<ROWS/8, 256>>>(m_Wi, m_Wf, m_bi, m_bf);
    mlstm_pre<<<BB*NHH/4, 128>>>();
    mlstm_attn<<<gAttn, 256>>>();
    gemm_mma<<<gRes, 256>>>(SEL_H, m_Wp, m_Wp, m_Wp, m_Wp, 2);

    // ---- sLSTM layer ----
    ln_kernel<<<ROWS, 256>>>(s_ln_g, s_ln_b);
    gemm_mma<<<gGate, 256>>>(SEL_XN, s_Wz, s_Wi, s_Wf, s_Wo, 1);
    slstm_scan<<<BB*NHH, 256>>>(s_Rz, s_Ri, s_Rf, s_Ro);
    gemm_mma<<<gRes, 256>>>(SEL_H, s_Wp, s_Wp, s_Wp, s_Wp, 2);

    // ---- mLSTM layer 1 ----
    ln_kernel<<<ROWS, 256>>>(m_ln_g + DD, m_ln_b + DD);
    gemm_mma<<<gGate, 256>>>(SEL_XN, m_Wq + DD*HH, m_Wk + DD*HH,
                             m_Wv + DD*HH, m_Wo + DD*HH, 0);
    ipfp_kernel<<<ROWS/8, 256>>>(m_Wi + DD*NHH, m_Wf + DD*NHH,
                                 m_bi + NHH, m_bf + NHH);
    mlstm_pre<<<BB*NHH/4, 128>>>();
    mlstm_attn<<<gAttn, 256>>>();
    gemm_mma<<<gRes, 256>>>(SEL_H, m_Wp + HH*DD, m_Wp + HH*DD,
                            m_Wp + HH*DD, m_Wp + HH*DD, 2);

    final_kernel<<<BB, 256>>>(fc_W, fc_b, out);
    (void)in_sizes; (void)n_in; (void)out_size;
}